// round 13
// baseline (speedup 1.0000x reference)
#include <cuda_runtime.h>

// ============================================================================
// STGCNEncoder — fused persistent kernel, v6 (one-pass histogram).
// Only row 0 of the GCN output feeds the GRU.
//  Phase 0: zero 400KB degree table (grid-strided) + per-block dtype detect.
//  Phase 1: ONE stream over dst: REDG histogram (fire-and-forget spread
//           atomics into L2-resident table) + collect srcs of dst==0 edges.
//  Phase 2: encoder GEMVs (block per term, degrees read from g_deg) + gh.
//  Phase 3: block-0 tail (xsum, g0, gi with 4-row ILP, gates, reset).
//  3 grid barriers. B=1024, G=148.
// ============================================================================

#define G    148
#define B    1024
#define STR  (G * B)
#define CAP  2048
#define DEGM 262144

__device__ unsigned long long g_bar;
__device__ int   g_cnt;                 // # dst==0 edges (reset in tail)
__device__ int   g_srcs[CAP];
__device__ int   g_deg[DEGM];           // edge in-degree histogram (re-zeroed ph0)
__device__ float g_ybuf[CAP + 1][128];
__device__ float g_gh[768];

__device__ __forceinline__ void gbar() {
    __threadfence();
    __syncthreads();
    if (threadIdx.x == 0) {
        unsigned long long t = atomicAdd(&g_bar, 1ULL);
        unsigned long long target = t - (t % G) + G;
        volatile unsigned long long* p = &g_bar;
        while (*p < target) __nanosleep(32);
    }
    __syncthreads();
    __threadfence();
}

__global__ void __launch_bounds__(B, 1) k_fused(
    const float* __restrict__ nf, const float* __restrict__ h,
    const float* __restrict__ W_enc, const float* __restrict__ b_enc,
    const float* __restrict__ W_gcn, const float* __restrict__ b_gcn,
    const float* __restrict__ W_ih, const float* __restrict__ W_hh,
    const float* __restrict__ b_ih, const float* __restrict__ b_hh,
    const unsigned* __restrict__ w, int E, int N, float* __restrict__ out)
{
    __shared__ int   sBad;
    __shared__ int   sS[CAP];
    __shared__ float sF[64];
    __shared__ float sTail[2048];        // tail reuse: sX|sG0|sGi|sPar

    const int t = threadIdx.x, lane = t & 31, wid = t >> 5;
    const int bid = blockIdx.x;
    const int gid = bid * B + t;

    // ---- Phase 0: zero degree table + dtype detect ----
    for (int i = gid; i < N; i += STR) g_deg[i] = 0;
    if (t == 0) sBad = 0;
    __syncthreads();
    {
        int bad = 0;
        for (int i = t; i < 2048 && i < E; i += B) bad |= (int)w[2 * i + 1];
        if (bad) atomicOr(&sBad, 1);
    }
    __syncthreads();
    const bool is64 = (sBad == 0);
    gbar();  // -------- barrier 1: table zeroed before any RED --------

    // ---- Phase 1: ONE stream: histogram + collect dst==0 srcs ----
    if (is64) {
        const long long* srcq = (const long long*)w;
        if ((E & 1) == 0) {
            const uint4* dv = (const uint4*)(w + 2L * E);   // {lo,hi,lo,hi}
            int nv = E >> 1;
            int i = gid;
            for (; i + 3 * STR < nv; i += 4 * STR) {
                uint4 v0 = dv[i], v1 = dv[i + STR], v2 = dv[i + 2 * STR], v3 = dv[i + 3 * STR];
                atomicAdd(&g_deg[v0.x], 1); atomicAdd(&g_deg[v0.z], 1);
                atomicAdd(&g_deg[v1.x], 1); atomicAdd(&g_deg[v1.z], 1);
                atomicAdd(&g_deg[v2.x], 1); atomicAdd(&g_deg[v2.z], 1);
                atomicAdd(&g_deg[v3.x], 1); atomicAdd(&g_deg[v3.z], 1);
                unsigned m = min(min(min(v0.x, v0.z), min(v1.x, v1.z)),
                                 min(min(v2.x, v2.z), min(v3.x, v3.z)));
                if (m == 0) {
                    uint4 vv[4] = {v0, v1, v2, v3};
                    #pragma unroll
                    for (int j = 0; j < 4; j++) {
                        long e = 2L * (i + j * STR);
                        if (vv[j].x == 0) { int p = atomicAdd(&g_cnt, 1); if (p < CAP) g_srcs[p] = (int)srcq[e]; }
                        if (vv[j].z == 0) { int p = atomicAdd(&g_cnt, 1); if (p < CAP) g_srcs[p] = (int)srcq[e + 1]; }
                    }
                }
            }
            for (; i < nv; i += STR) {
                uint4 v = dv[i];
                atomicAdd(&g_deg[v.x], 1); atomicAdd(&g_deg[v.z], 1);
                if (min(v.x, v.z) == 0) {
                    long e = 2L * i;
                    if (v.x == 0) { int p = atomicAdd(&g_cnt, 1); if (p < CAP) g_srcs[p] = (int)srcq[e]; }
                    if (v.z == 0) { int p = atomicAdd(&g_cnt, 1); if (p < CAP) g_srcs[p] = (int)srcq[e + 1]; }
                }
            }
        } else {
            const long long* dst = srcq + E;
            for (long i = gid; i < E; i += STR) {
                int d = (int)dst[i];
                atomicAdd(&g_deg[d], 1);
                if (d == 0) { int p = atomicAdd(&g_cnt, 1); if (p < CAP) g_srcs[p] = (int)srcq[i]; }
            }
        }
    } else {
        const int* srci = (const int*)w;
        if ((E & 3) == 0) {
            const uint4* dv = (const uint4*)(w + E);
            int nv = E >> 2;
            int i = gid;
            for (; i + STR < nv; i += 2 * STR) {
                uint4 v0 = dv[i], v1 = dv[i + STR];
                atomicAdd(&g_deg[v0.x], 1); atomicAdd(&g_deg[v0.y], 1);
                atomicAdd(&g_deg[v0.z], 1); atomicAdd(&g_deg[v0.w], 1);
                atomicAdd(&g_deg[v1.x], 1); atomicAdd(&g_deg[v1.y], 1);
                atomicAdd(&g_deg[v1.z], 1); atomicAdd(&g_deg[v1.w], 1);
                unsigned m = min(min(min(v0.x, v0.y), min(v0.z, v0.w)),
                                 min(min(v1.x, v1.y), min(v1.z, v1.w)));
                if (m == 0) {
                    uint4 vv[2] = {v0, v1};
                    #pragma unroll
                    for (int j = 0; j < 2; j++) {
                        long e = 4L * (i + j * STR);
                        if (vv[j].x == 0) { int p = atomicAdd(&g_cnt, 1); if (p < CAP) g_srcs[p] = srci[e]; }
                        if (vv[j].y == 0) { int p = atomicAdd(&g_cnt, 1); if (p < CAP) g_srcs[p] = srci[e + 1]; }
                        if (vv[j].z == 0) { int p = atomicAdd(&g_cnt, 1); if (p < CAP) g_srcs[p] = srci[e + 2]; }
                        if (vv[j].w == 0) { int p = atomicAdd(&g_cnt, 1); if (p < CAP) g_srcs[p] = srci[e + 3]; }
                    }
                }
            }
            for (; i < nv; i += STR) {
                uint4 v = dv[i];
                atomicAdd(&g_deg[v.x], 1); atomicAdd(&g_deg[v.y], 1);
                atomicAdd(&g_deg[v.z], 1); atomicAdd(&g_deg[v.w], 1);
                if (min(min(v.x, v.y), min(v.z, v.w)) == 0) {
                    long e = 4L * i;
                    if (v.x == 0) { int p = atomicAdd(&g_cnt, 1); if (p < CAP) g_srcs[p] = srci[e]; }
                    if (v.y == 0) { int p = atomicAdd(&g_cnt, 1); if (p < CAP) g_srcs[p] = srci[e + 1]; }
                    if (v.z == 0) { int p = atomicAdd(&g_cnt, 1); if (p < CAP) g_srcs[p] = srci[e + 2]; }
                    if (v.w == 0) { int p = atomicAdd(&g_cnt, 1); if (p < CAP) g_srcs[p] = srci[e + 3]; }
                }
            }
        } else {
            const int* dst = srci + E;
            for (long i = gid; i < E; i += STR) {
                int d = dst[i];
                atomicAdd(&g_deg[d], 1);
                if (d == 0) { int p = atomicAdd(&g_cnt, 1); if (p < CAP) g_srcs[p] = srci[i]; }
            }
        }
    }
    gbar();  // -------- barrier 2 --------

    int cnt = g_cnt; if (cnt > CAP) cnt = CAP;
    const int M = cnt + 1;                      // + node-0 self-loop term

    // stage srcs (encoder blocks only need them, but staging is cheap)
    for (int i = t; i < cnt; i += B) sS[i] = g_srcs[i];
    __syncthreads();

    // ---- Phase 2: encoder terms (block per term) + gh overlap ----
    if (bid < M) {
        const float rd0 = rsqrtf((float)g_deg[0] + 1.0f);   // +1 self loop
        for (int i = bid; i < M; i += G) {
            int s = (i < cnt) ? sS[i] : 0;
            float wt = rsqrtf((float)g_deg[s] + 1.0f) * rd0;
            if (t < 64) sF[t] = nf[(long)s * 64 + t];
            __syncthreads();
            float f0 = sF[lane], f1 = sF[lane + 32];
            #pragma unroll
            for (int jj = 0; jj < 4; jj++) {
                int j = wid * 4 + jj;
                const float* wr = W_enc + j * 64;
                float a = wr[lane] * f0 + wr[lane + 32] * f1;
                #pragma unroll
                for (int o = 16; o; o >>= 1) a += __shfl_down_sync(0xffffffffu, a, o);
                if (lane == 0) g_ybuf[i][j] = wt * fmaxf(a + b_enc[j], 0.0f);
            }
            __syncthreads();
        }
    }
    if (bid >= 96) {                      // gh = W_hh @ h + b_hh (indep of g0)
        int r = (bid - 96) * 32 + wid;
        if (r < 768) {
            const float* wr = W_hh + r * 256;
            float a = 0.0f;
            #pragma unroll
            for (int kk = 0; kk < 8; kk++) a += wr[kk * 32 + lane] * h[kk * 32 + lane];
            #pragma unroll
            for (int o = 16; o; o >>= 1) a += __shfl_down_sync(0xffffffffu, a, o);
            if (lane == 0) g_gh[r] = a + b_hh[r];
        }
    }
    gbar();  // -------- barrier 3 --------

    // ---- Phase 3: block-0 tail: xsum, g0, gi (4-row ILP), gates, reset ----
    if (bid == 0) {
        float* sX   = sTail;               // 128
        float* sG0  = sTail + 128;         // 128
        float* sGi  = sTail + 256;         // 768
        float* sPar = sTail + 1024;        // 8 x 128

        {   // parallel xsum, deterministic fixed-order groups
            int grp = t >> 7, col = t & 127;
            float xs = 0.0f;
            for (int i = grp; i < M; i += 8) xs += g_ybuf[i][col];
            sPar[grp * 128 + col] = xs;
        }
        __syncthreads();
        if (t < 128) {
            float s = 0.0f;
            #pragma unroll
            for (int g2 = 0; g2 < 8; g2++) s += sPar[g2 * 128 + t];
            sX[t] = s;
        }
        __syncthreads();
        #pragma unroll
        for (int jj = 0; jj < 4; jj++) {
            int j = wid * 4 + jj;
            float a = 0.0f;
            #pragma unroll
            for (int kk = 0; kk < 4; kk++)
                a += W_gcn[j * 128 + kk * 32 + lane] * sX[kk * 32 + lane];
            #pragma unroll
            for (int o = 16; o; o >>= 1) a += __shfl_down_sync(0xffffffffu, a, o);
            if (lane == 0) sG0[j] = fmaxf(a + b_gcn[j], 0.0f);
        }
        __syncthreads();
        // gi: 24 rows/warp in 6 batches of 4 (independent reduce chains pipeline)
        float x0 = sG0[lane], x1 = sG0[32 + lane], x2 = sG0[64 + lane], x3 = sG0[96 + lane];
        #pragma unroll
        for (int q = 0; q < 24; q += 4) {
            int r0 = (q + 0) * 32 + wid, r1 = (q + 1) * 32 + wid;
            int r2 = (q + 2) * 32 + wid, r3 = (q + 3) * 32 + wid;
            const float* w0 = W_ih + r0 * 128;
            const float* w1 = W_ih + r1 * 128;
            const float* w2 = W_ih + r2 * 128;
            const float* w3 = W_ih + r3 * 128;
            float a0 = w0[lane] * x0 + w0[32 + lane] * x1 + w0[64 + lane] * x2 + w0[96 + lane] * x3;
            float a1 = w1[lane] * x0 + w1[32 + lane] * x1 + w1[64 + lane] * x2 + w1[96 + lane] * x3;
            float a2 = w2[lane] * x0 + w2[32 + lane] * x1 + w2[64 + lane] * x2 + w2[96 + lane] * x3;
            float a3 = w3[lane] * x0 + w3[32 + lane] * x1 + w3[64 + lane] * x2 + w3[96 + lane] * x3;
            #pragma unroll
            for (int o = 16; o; o >>= 1) {
                a0 += __shfl_down_sync(0xffffffffu, a0, o);
                a1 += __shfl_down_sync(0xffffffffu, a1, o);
                a2 += __shfl_down_sync(0xffffffffu, a2, o);
                a3 += __shfl_down_sync(0xffffffffu, a3, o);
            }
            if (lane == 0) {
                sGi[r0] = a0 + b_ih[r0];
                sGi[r1] = a1 + b_ih[r1];
                sGi[r2] = a2 + b_ih[r2];
                sGi[r3] = a3 + b_ih[r3];
            }
        }
        __syncthreads();
        if (t < 256) {
            float r_ = 1.0f / (1.0f + expf(-(sGi[t] + g_gh[t])));
            float z  = 1.0f / (1.0f + expf(-(sGi[256 + t] + g_gh[256 + t])));
            float nn = tanhf(sGi[512 + t] + r_ * g_gh[512 + t]);
            out[t] = (1.0f - z) * nn + z * h[t];
        }
        if (t == 0) g_cnt = 0;             // table re-zeroed in phase 0 next call
    }
}

// ---------------------------------------------------------------------------
extern "C" void kernel_launch(void* const* d_in, const int* in_sizes, int n_in,
                              void* d_out, int out_size) {
    const float* nf    = (const float*)d_in[0];
    // d_in[1] = edge_attr (unused by reference)
    const float* h     = (const float*)d_in[2];
    const float* W_enc = (const float*)d_in[3];
    const float* b_enc = (const float*)d_in[4];
    const float* W_gcn = (const float*)d_in[5];
    const float* b_gcn = (const float*)d_in[6];
    const float* W_ih  = (const float*)d_in[7];
    const float* W_hh  = (const float*)d_in[8];
    const float* b_ih  = (const float*)d_in[9];
    const float* b_hh  = (const float*)d_in[10];
    const unsigned* ei = (const unsigned*)d_in[11];
    int E = in_sizes[11] / 2;
    int N = in_sizes[0] / 64;
    if (N > DEGM) N = DEGM;
    float* out = (float*)d_out;

    k_fused<<<G, B>>>(nf, h, W_enc, b_enc, W_gcn, b_gcn,
                      W_ih, W_hh, b_ih, b_hh, ei, E, N, out);
}

// round 14
// speedup vs baseline: 1.7990x; 1.7990x over previous
#include <cuda_runtime.h>

// ============================================================================
// STGCNEncoder — fused persistent kernel, v7 (2 blocks/SM residency).
// Only row 0 of the GCN output feeds the GRU.
//  Pass A: stream dst, unsigned-min trick finds dst==0 edges.
//  Pass B: u8 presence table in dynamic smem -> exact degrees of the ~34 set.
//  G=296 (2 CTAs/SM), B=1024 -> 2048 threads/SM: streaming phases are
//  latency-bound and scale with resident warps (evidence: R2 vs R12 histogram,
//  R9-R11 pass-variant neutrality at 1024 thr/SM).
//  3 grid barriers. Encoder + gh overlap; block-0 tail.
// ============================================================================

#define G    296
#define B    1024
#define STR  (G * B)
#define CAP  2048
#define U    2

__device__ unsigned long long g_bar;
__device__ int   g_cnt;
__device__ int   g_srcs[CAP];
__device__ int   g_nodecnt[CAP + 2];
__device__ unsigned short g_pres[131072];   // fallback presence (cnt>253, rare)
__device__ float g_ybuf[CAP + 1][128];
__device__ float g_gh[768];

extern __shared__ char sMem[];              // u8 presence table (NPAD bytes); tail reuse

__device__ __forceinline__ void gbar() {
    __threadfence();
    __syncthreads();
    if (threadIdx.x == 0) {
        unsigned long long t = atomicAdd(&g_bar, 1ULL);
        unsigned long long target = t - (t % G) + G;
        volatile unsigned long long* p = &g_bar;
        while (*p < target) {}
    }
    __syncthreads();
    __threadfence();
}

__global__ void __launch_bounds__(B, 2) k_fused(
    const float* __restrict__ nf, const float* __restrict__ h,
    const float* __restrict__ W_enc, const float* __restrict__ b_enc,
    const float* __restrict__ W_gcn, const float* __restrict__ b_gcn,
    const float* __restrict__ W_ih, const float* __restrict__ W_hh,
    const float* __restrict__ b_ih, const float* __restrict__ b_hh,
    const unsigned* __restrict__ w, int E, int N, float* __restrict__ out)
{
    __shared__ int   sBad;
    __shared__ float sF[64];
    __shared__ int   sS[CAP];

    const int t = threadIdx.x, lane = t & 31, wid = t >> 5;
    const int bid = blockIdx.x;
    const int gid = bid * B + t;
    const int NPAD = (N + 15) & ~15;
    unsigned char* sT8 = (unsigned char*)sMem;

    // ---- init: zero u8 table + dtype detect (per block) ----
    {
        uint4* p4 = (uint4*)sMem;
        uint4 z = make_uint4(0, 0, 0, 0);
        for (int i = t; i < (NPAD >> 4); i += B) p4[i] = z;
    }
    if (t == 0) sBad = 0;
    __syncthreads();
    {
        int bad = 0;
        for (int i = t; i < 2048 && i < E; i += B) bad |= (int)w[2 * i + 1];
        if (bad) atomicOr(&sBad, 1);
    }
    __syncthreads();
    const bool is64 = (sBad == 0);
    const bool fastA = is64 ? ((E & 1) == 0) : ((E & 3) == 0);

    // ---------------- Pass A: collect srcs of dst==0 edges ----------------
    if (is64) {
        const long long* srcq = (const long long*)w;
        if (fastA) {
            const uint4* dv = (const uint4*)(w + 2L * E);  // {lo,hi,lo,hi}
            int nv = E >> 1;
            int i = gid;
            for (; i + (U - 1) * STR < nv; i += U * STR) {
                uint4 v0 = dv[i], v1 = dv[i + STR];
                if (min(min(v0.x, v0.z), min(v1.x, v1.z)) == 0) {
                    long e0 = 2L * i, e1 = 2L * (i + STR);
                    if (v0.x == 0) { int p = atomicAdd(&g_cnt, 1); if (p < CAP) g_srcs[p] = (int)srcq[e0]; }
                    if (v0.z == 0) { int p = atomicAdd(&g_cnt, 1); if (p < CAP) g_srcs[p] = (int)srcq[e0 + 1]; }
                    if (v1.x == 0) { int p = atomicAdd(&g_cnt, 1); if (p < CAP) g_srcs[p] = (int)srcq[e1]; }
                    if (v1.z == 0) { int p = atomicAdd(&g_cnt, 1); if (p < CAP) g_srcs[p] = (int)srcq[e1 + 1]; }
                }
            }
            for (; i < nv; i += STR) {
                uint4 v = dv[i];
                if (min(v.x, v.z) == 0) {
                    long e = 2L * i;
                    if (v.x == 0) { int p = atomicAdd(&g_cnt, 1); if (p < CAP) g_srcs[p] = (int)srcq[e]; }
                    if (v.z == 0) { int p = atomicAdd(&g_cnt, 1); if (p < CAP) g_srcs[p] = (int)srcq[e + 1]; }
                }
            }
        } else {
            const long long* dst = srcq + E;
            for (long i = gid; i < E; i += STR)
                if (dst[i] == 0) { int p = atomicAdd(&g_cnt, 1); if (p < CAP) g_srcs[p] = (int)srcq[i]; }
        }
    } else {
        const int* srci = (const int*)w;
        if (fastA) {
            const uint4* dv = (const uint4*)(w + E);
            int nv = E >> 2;
            int i = gid;
            for (; i + (U - 1) * STR < nv; i += U * STR) {
                uint4 v0 = dv[i], v1 = dv[i + STR];
                unsigned m = min(min(min(v0.x, v0.y), min(v0.z, v0.w)),
                                 min(min(v1.x, v1.y), min(v1.z, v1.w)));
                if (m == 0) {
                    long e0 = 4L * i, e1 = 4L * (i + STR);
                    if (v0.x == 0) { int p = atomicAdd(&g_cnt, 1); if (p < CAP) g_srcs[p] = srci[e0]; }
                    if (v0.y == 0) { int p = atomicAdd(&g_cnt, 1); if (p < CAP) g_srcs[p] = srci[e0 + 1]; }
                    if (v0.z == 0) { int p = atomicAdd(&g_cnt, 1); if (p < CAP) g_srcs[p] = srci[e0 + 2]; }
                    if (v0.w == 0) { int p = atomicAdd(&g_cnt, 1); if (p < CAP) g_srcs[p] = srci[e0 + 3]; }
                    if (v1.x == 0) { int p = atomicAdd(&g_cnt, 1); if (p < CAP) g_srcs[p] = srci[e1]; }
                    if (v1.y == 0) { int p = atomicAdd(&g_cnt, 1); if (p < CAP) g_srcs[p] = srci[e1 + 1]; }
                    if (v1.z == 0) { int p = atomicAdd(&g_cnt, 1); if (p < CAP) g_srcs[p] = srci[e1 + 2]; }
                    if (v1.w == 0) { int p = atomicAdd(&g_cnt, 1); if (p < CAP) g_srcs[p] = srci[e1 + 3]; }
                }
            }
            for (; i < nv; i += STR) {
                uint4 v = dv[i];
                if (min(min(v.x, v.y), min(v.z, v.w)) == 0) {
                    long e = 4L * i;
                    if (v.x == 0) { int p = atomicAdd(&g_cnt, 1); if (p < CAP) g_srcs[p] = srci[e]; }
                    if (v.y == 0) { int p = atomicAdd(&g_cnt, 1); if (p < CAP) g_srcs[p] = srci[e + 1]; }
                    if (v.z == 0) { int p = atomicAdd(&g_cnt, 1); if (p < CAP) g_srcs[p] = srci[e + 2]; }
                    if (v.w == 0) { int p = atomicAdd(&g_cnt, 1); if (p < CAP) g_srcs[p] = srci[e + 3]; }
                }
            }
        } else {
            const int* dst = srci + E;
            for (long i = gid; i < E; i += STR)
                if (dst[i] == 0) { int p = atomicAdd(&g_cnt, 1); if (p < CAP) g_srcs[p] = srci[i]; }
        }
    }
    gbar();  // -------- barrier 1 --------

    int cnt = g_cnt; if (cnt > CAP) cnt = CAP;
    const int M = cnt + 1;                      // + node-0 self-loop term
    const bool fastB = (cnt <= 253);

    // stage srcs into smem (encoder + table build)
    for (int i = t; i < cnt; i += B) sS[i] = g_srcs[i];
    __syncthreads();

    // ---------------- Pass B: count set-membership over dst ----------------
    if (fastB) {
        // parallel u8 table build (duplicate races are value-equivalent)
        for (int i = t; i < cnt; i += B) sT8[sS[i]] = (unsigned char)(i + 1);
        __syncthreads();
        if (t == 0 && sT8[0] == 0) sT8[0] = (unsigned char)(cnt + 1);
        __syncthreads();

        if (is64) {
            if (fastA) {
                const uint4* dv = (const uint4*)(w + 2L * E);
                int nv = E >> 1;
                int i = gid;
                for (; i + (U - 1) * STR < nv; i += U * STR) {
                    uint4 v0 = dv[i], v1 = dv[i + STR];
                    unsigned p0 = sT8[v0.x], p1 = sT8[v0.z];
                    unsigned p2 = sT8[v1.x], p3 = sT8[v1.z];
                    if ((p0 | p1) | (p2 | p3)) {
                        if (p0) atomicAdd(&g_nodecnt[p0 - 1], 1);
                        if (p1) atomicAdd(&g_nodecnt[p1 - 1], 1);
                        if (p2) atomicAdd(&g_nodecnt[p2 - 1], 1);
                        if (p3) atomicAdd(&g_nodecnt[p3 - 1], 1);
                    }
                }
                for (; i < nv; i += STR) {
                    uint4 v = dv[i];
                    unsigned p0 = sT8[v.x], p1 = sT8[v.z];
                    if (p0) atomicAdd(&g_nodecnt[p0 - 1], 1);
                    if (p1) atomicAdd(&g_nodecnt[p1 - 1], 1);
                }
            } else {
                const long long* dst = ((const long long*)w) + E;
                for (long i = gid; i < E; i += STR) {
                    unsigned p = sT8[(unsigned)dst[i]];
                    if (p) atomicAdd(&g_nodecnt[p - 1], 1);
                }
            }
        } else {
            if (fastA) {
                const uint4* dv = (const uint4*)(w + E);
                int nv = E >> 2;
                int i = gid;
                for (; i + (U - 1) * STR < nv; i += U * STR) {
                    uint4 v0 = dv[i], v1 = dv[i + STR];
                    unsigned p0 = sT8[v0.x], p1 = sT8[v0.y], p2 = sT8[v0.z], p3 = sT8[v0.w];
                    unsigned q0 = sT8[v1.x], q1 = sT8[v1.y], q2 = sT8[v1.z], q3 = sT8[v1.w];
                    if (((p0 | p1) | (p2 | p3)) | ((q0 | q1) | (q2 | q3))) {
                        if (p0) atomicAdd(&g_nodecnt[p0 - 1], 1);
                        if (p1) atomicAdd(&g_nodecnt[p1 - 1], 1);
                        if (p2) atomicAdd(&g_nodecnt[p2 - 1], 1);
                        if (p3) atomicAdd(&g_nodecnt[p3 - 1], 1);
                        if (q0) atomicAdd(&g_nodecnt[q0 - 1], 1);
                        if (q1) atomicAdd(&g_nodecnt[q1 - 1], 1);
                        if (q2) atomicAdd(&g_nodecnt[q2 - 1], 1);
                        if (q3) atomicAdd(&g_nodecnt[q3 - 1], 1);
                    }
                }
                for (; i < nv; i += STR) {
                    uint4 v = dv[i];
                    unsigned p0 = sT8[v.x], p1 = sT8[v.y], p2 = sT8[v.z], p3 = sT8[v.w];
                    if (p0) atomicAdd(&g_nodecnt[p0 - 1], 1);
                    if (p1) atomicAdd(&g_nodecnt[p1 - 1], 1);
                    if (p2) atomicAdd(&g_nodecnt[p2 - 1], 1);
                    if (p3) atomicAdd(&g_nodecnt[p3 - 1], 1);
                }
            } else {
                const int* dst = ((const int*)w) + E;
                for (long i = gid; i < E; i += STR) {
                    unsigned p = sT8[(unsigned)dst[i]];
                    if (p) atomicAdd(&g_nodecnt[p - 1], 1);
                }
            }
        }
    } else {
        // fallback: global u16 presence table (cnt > 253 — practically never)
        for (int i = bid * B + t; i < 131072; i += STR) g_pres[i] = 0;
        gbar();
        if (bid == 0 && t == 0) {
            for (int i = 0; i < cnt; i++) g_pres[sS[i]] = (unsigned short)(i + 1);
            if (g_pres[0] == 0) g_pres[0] = (unsigned short)(cnt + 1);
        }
        gbar();
        if (is64) {
            const long long* dst = ((const long long*)w) + E;
            for (long i = gid; i < E; i += STR) {
                unsigned p = g_pres[(unsigned)dst[i]];
                if (p) atomicAdd(&g_nodecnt[p - 1], 1);
            }
        } else {
            const int* dst = ((const int*)w) + E;
            for (long i = gid; i < E; i += STR) {
                unsigned p = g_pres[(unsigned)dst[i]];
                if (p) atomicAdd(&g_nodecnt[p - 1], 1);
            }
        }
    }
    gbar();  // -------- barrier 2 --------

    // ---------------- Encoder terms (block per term) + gh overlap ----------
    if (bid < M) {
        unsigned pi0 = fastB ? (unsigned)sT8[0] : (unsigned)g_pres[0];
        const float rd0 = rsqrtf((float)g_nodecnt[pi0 - 1] + 1.0f);
        for (int i = bid; i < M; i += G) {
            int s = (i < cnt) ? sS[i] : 0;
            unsigned pis = fastB ? (unsigned)sT8[s] : (unsigned)g_pres[s];
            float wt = rsqrtf((float)g_nodecnt[pis - 1] + 1.0f) * rd0;
            if (t < 64) sF[t] = nf[(long)s * 64 + t];
            __syncthreads();
            float f0 = sF[lane], f1 = sF[lane + 32];
            #pragma unroll
            for (int jj = 0; jj < 4; jj++) {
                int j = wid * 4 + jj;
                const float* wr = W_enc + j * 64;
                float a = wr[lane] * f0 + wr[lane + 32] * f1;
                #pragma unroll
                for (int o = 16; o; o >>= 1) a += __shfl_down_sync(0xffffffffu, a, o);
                if (lane == 0) g_ybuf[i][j] = wt * fmaxf(a + b_enc[j], 0.0f);
            }
            __syncthreads();
        }
    }
    if (bid >= 272) {                     // gh = W_hh @ h + b_hh (indep of g0)
        int r = (bid - 272) * 32 + wid;   // 24 blocks x 32 warps = 768 rows
        if (r < 768) {
            const float* wr = W_hh + r * 256;
            float a = 0.0f;
            #pragma unroll
            for (int kk = 0; kk < 8; kk++) a += wr[kk * 32 + lane] * h[kk * 32 + lane];
            #pragma unroll
            for (int o = 16; o; o >>= 1) a += __shfl_down_sync(0xffffffffu, a, o);
            if (lane == 0) g_gh[r] = a + b_hh[r];
        }
    }
    gbar();  // -------- barrier 3 --------

    // ---------------- Block-0 tail: xsum, g0, gi, gates, reset -------------
    if (bid == 0) {
        float* sX   = (float*)sMem;       // table no longer needed: reuse smem
        float* sG0  = sX + 128;
        float* sGi  = sG0 + 128;          // 768 floats
        float* sPar = sX + 1024;          // 8 x 128 partials

        {   // parallel xsum, deterministic fixed-order groups
            int grp = t >> 7, col = t & 127;
            float xs = 0.0f;
            for (int i = grp; i < M; i += 8) xs += g_ybuf[i][col];
            sPar[grp * 128 + col] = xs;
        }
        __syncthreads();
        if (t < 128) {
            float s = 0.0f;
            #pragma unroll
            for (int g2 = 0; g2 < 8; g2++) s += sPar[g2 * 128 + t];
            sX[t] = s;
        }
        __syncthreads();
        #pragma unroll
        for (int jj = 0; jj < 4; jj++) {
            int j = wid * 4 + jj;
            float a = 0.0f;
            #pragma unroll
            for (int kk = 0; kk < 4; kk++)
                a += W_gcn[j * 128 + kk * 32 + lane] * sX[kk * 32 + lane];
            #pragma unroll
            for (int o = 16; o; o >>= 1) a += __shfl_down_sync(0xffffffffu, a, o);
            if (lane == 0) sG0[j] = fmaxf(a + b_gcn[j], 0.0f);
        }
        __syncthreads();
        #pragma unroll
        for (int q = 0; q < 24; q++) {
            int r = q * 32 + wid;
            const float* wr = W_ih + r * 128;
            float a = 0.0f;
            #pragma unroll
            for (int kk = 0; kk < 4; kk++)
                a += wr[kk * 32 + lane] * sG0[kk * 32 + lane];
            #pragma unroll
            for (int o = 16; o; o >>= 1) a += __shfl_down_sync(0xffffffffu, a, o);
            if (lane == 0) sGi[r] = a + b_ih[r];
        }
        __syncthreads();
        if (t < 256) {
            float r_ = 1.0f / (1.0f + expf(-(sGi[t] + g_gh[t])));
            float z  = 1.0f / (1.0f + expf(-(sGi[256 + t] + g_gh[256 + t])));
            float nn = tanhf(sGi[512 + t] + r_ * g_gh[512 + t]);
            out[t] = (1.0f - z) * nn + z * h[t];
        }
        for (int i = t; i < cnt + 2; i += B) g_nodecnt[i] = 0;
        if (t == 0) g_cnt = 0;
    }
}

// ---------------------------------------------------------------------------
extern "C" void kernel_launch(void* const* d_in, const int* in_sizes, int n_in,
                              void* d_out, int out_size) {
    const float* nf    = (const float*)d_in[0];
    // d_in[1] = edge_attr (unused by reference)
    const float* h     = (const float*)d_in[2];
    const float* W_enc = (const float*)d_in[3];
    const float* b_enc = (const float*)d_in[4];
    const float* W_gcn = (const float*)d_in[5];
    const float* b_gcn = (const float*)d_in[6];
    const float* W_ih  = (const float*)d_in[7];
    const float* W_hh  = (const float*)d_in[8];
    const float* b_ih  = (const float*)d_in[9];
    const float* b_hh  = (const float*)d_in[10];
    const unsigned* ei = (const unsigned*)d_in[11];
    int E = in_sizes[11] / 2;
    int N = in_sizes[0] / 64;
    float* out = (float*)d_out;

    int npad = (N + 15) & ~15;
    int smem = npad;
    if (smem < 16384) smem = 16384;                // room for tail reuse arrays
    cudaFuncSetAttribute(k_fused, cudaFuncAttributeMaxDynamicSharedMemorySize, smem);

    k_fused<<<G, B, smem>>>(nf, h, W_enc, b_enc, W_gcn, b_gcn,
                            W_ih, W_hh, b_ih, b_hh, ei, E, N, out);
}